// round 14
// baseline (speedup 1.0000x reference)
#include <cuda_runtime.h>
#include <cstdint>

#define B_ 8
#define M_ 2048
#define N_ 2048
#define R_ 32

#define L1C 10.24f
#define L2C 10.24f
#define EPSC 1e-16f

// Scratch (device globals; no allocation allowed)
__device__ float g_bp[16 * B_ * R_ * R_];  // gram partials

// ---- bf16 helpers -------------------------------------------------------
__device__ __forceinline__ uint32_t pack2bf(float lo, float hi) {   // mem order [lo,hi]
    uint32_t r; asm("cvt.rn.bf16x2.f32 %0, %1, %2;" : "=r"(r) : "f"(hi), "f"(lo)); return r;
}
__device__ __forceinline__ uint16_t cvt1(float x) {
    uint16_t h; asm("cvt.rn.bf16.f32 %0, %1;" : "=h"(h) : "f"(x)); return h;
}
__device__ __forceinline__ float bf2f(uint16_t h) {
    return __uint_as_float(((uint32_t)h) << 16);
}
__device__ __forceinline__ void mma16816(float* c, const uint32_t* a, uint32_t b0, uint32_t b1) {
    asm volatile(
        "mma.sync.aligned.m16n8k16.row.col.f32.bf16.bf16.f32 "
        "{%0,%1,%2,%3}, {%4,%5,%6,%7}, {%8,%9}, {%0,%1,%2,%3};"
        : "+f"(c[0]), "+f"(c[1]), "+f"(c[2]), "+f"(c[3])
        : "r"(a[0]), "r"(a[1]), "r"(a[2]), "r"(a[3]), "r"(b0), "r"(b1));
}

// ======================= gram partial kernel =======================
#define GCHUNK 128
__global__ void gram_partial_kernel(const float* __restrict__ vin) {
    __shared__ float vs[GCHUNK][R_];
    int b = blockIdx.y, p = blockIdx.x, tid = threadIdx.x;
    const float4* src = (const float4*)(vin + ((size_t)b * N_ + p * GCHUNK) * R_);
    float4* dst = (float4*)&vs[0][0];
#pragma unroll
    for (int i = 0; i < 4; i++) dst[tid + 256 * i] = src[tid + 256 * i];
    __syncthreads();
    int r = tid >> 3, s4 = (tid & 7) * 4;
    float ax = 0.f, ay = 0.f, az = 0.f, aw = 0.f;
#pragma unroll 8
    for (int m = 0; m < GCHUNK; m++) {
        float vr = vs[m][r];
        float4 sv = *(const float4*)&vs[m][s4];
        ax += vr * sv.x; ay += vr * sv.y; az += vr * sv.z; aw += vr * sv.w;
    }
    float* o = g_bp + ((size_t)p * B_ + b) * (R_ * R_) + r * R_ + s4;
    o[0] = ax; o[1] = ay; o[2] = az; o[3] = aw;
}

// In-kernel gram reduce: bs[1024 floats] = sum of 16 partials (fixed order).
// 128 threads, 2 float4 each. Caller syncs afterwards.
__device__ __forceinline__ void load_gram(float* bs_flat, int b, int tid) {
    const float4* bp = (const float4*)g_bp;
#pragma unroll
    for (int h = 0; h < 2; h++) {
        int j = tid + 128 * h;
        float4 s = {0.f, 0.f, 0.f, 0.f};
#pragma unroll
        for (int p = 0; p < 16; p++) {
            float4 t = bp[((size_t)p * B_ + b) * 256 + j];
            s.x += t.x; s.y += t.y; s.z += t.z; s.w += t.w;
        }
        ((float4*)bs_flat)[j] = s;
    }
}

// ======================= shared fragment compute =======================
template <int AST>
__device__ __forceinline__ void mma_kstep(const uint16_t* __restrict__ Ahi,
                                          const uint16_t* __restrict__ Alo,
                                          const uint16_t* __restrict__ Bhi,
                                          const uint16_t* __restrict__ Blo,
                                          int wrow, int g, int t4, int k16,
                                          float acc[4][4]) {
    uint32_t ah[4], al[4];
    int r0 = (wrow + g) * AST, r1 = (wrow + g + 8) * AST;
    int c0 = k16 + t4 * 2;
    ah[0] = *(const uint32_t*)&Ahi[r0 + c0];
    ah[1] = *(const uint32_t*)&Ahi[r1 + c0];
    ah[2] = *(const uint32_t*)&Ahi[r0 + c0 + 8];
    ah[3] = *(const uint32_t*)&Ahi[r1 + c0 + 8];
    al[0] = *(const uint32_t*)&Alo[r0 + c0];
    al[1] = *(const uint32_t*)&Alo[r1 + c0];
    al[2] = *(const uint32_t*)&Alo[r0 + c0 + 8];
    al[3] = *(const uint32_t*)&Alo[r1 + c0 + 8];
#pragma unroll
    for (int j = 0; j < 4; j++) {
        int nb = (j * 8 + g) * AST;
        uint32_t bh0 = *(const uint32_t*)&Bhi[nb + c0];
        uint32_t bh1 = *(const uint32_t*)&Bhi[nb + c0 + 8];
        uint32_t bl0 = *(const uint32_t*)&Blo[nb + c0];
        uint32_t bl1 = *(const uint32_t*)&Blo[nb + c0 + 8];
        mma16816(acc[j], ah, bh0, bh1);   // hi*hi
        mma16816(acc[j], ah, bl0, bl1);   // hi*lo
        mma16816(acc[j], al, bh0, bh1);   // lo*hi
    }
}

// Fused epilogue (64-row tile): acc -> res[64][33]; 64 threads run per-row CD.
__device__ __forceinline__ void fused_cd_epilogue(
    float acc[4][4], float* __restrict__ res /* [64][33] smem */,
    const float (*bs)[R_], const float* __restrict__ inv,
    const float* __restrict__ uin_rows, float* __restrict__ uout_rows,
    int tid, int wrow, int g, int t4) {
#pragma unroll
    for (int j = 0; j < 4; j++) {
        int c = j * 8 + t4 * 2;
        res[(wrow + g) * 33 + c]     = acc[j][0];
        res[(wrow + g) * 33 + c + 1] = acc[j][1];
        res[(wrow + g + 8) * 33 + c]     = acc[j][2];
        res[(wrow + g + 8) * 33 + c + 1] = acc[j][3];
    }
    __syncthreads();

    if (tid < 64) {
        const float* ur = uin_rows + (size_t)tid * R_;
        const float* arow = res + tid * 33;
        float ureg[R_];
#pragma unroll
        for (int i = 0; i < 8; i++) {
            float4 t2 = *(const float4*)(ur + i * 4);
            ureg[4 * i + 0] = t2.x; ureg[4 * i + 1] = t2.y;
            ureg[4 * i + 2] = t2.z; ureg[4 * i + 3] = t2.w;
        }
#pragma unroll
        for (int r = 0; r < R_; r++) {
            float brr = bs[r][r];
            float d0 = 0.f, d1 = 0.f, d2 = 0.f, d3 = 0.f;
#pragma unroll
            for (int k = 0; k < R_; k += 4) {
                d0 += ureg[k + 0] * bs[k + 0][r];
                d1 += ureg[k + 1] * bs[k + 1][r];
                d2 += ureg[k + 2] * bs[k + 2][r];
                d3 += ureg[k + 3] * bs[k + 3][r];
            }
            float dot = (d0 + d1) + (d2 + d3);
            float z = arow[r] - (dot - ureg[r] * brr);
            float num = (z > L1C) ? (z - L1C) : ((z < -L1C) ? (z + L1C) : 0.0f);
            ureg[r] = (num + EPSC) * inv[r];
        }
        float* outr = uout_rows + (size_t)tid * R_;
#pragma unroll
        for (int i = 0; i < 8; i++) {
            float4 o = {ureg[4 * i + 0], ureg[4 * i + 1], ureg[4 * i + 2], ureg[4 * i + 3]};
            *(float4*)(outr + i * 4) = o;
        }
    }
}

// ======================= pass 1: uout = CD(x @ v, uin) =======================
// grid (M_/64, B_) = 256 CTAs, 128 threads (4 warps x 16 rows). KT=64, stride 72.
// Buffers 2 x 27648B -> 3-4 CTAs/SM for cross-CTA latency hiding.
#define KT1 64
#define AST1 72
#define BUF1 27648   // Ahi 9216 | Alo 9216 | Bhi 4608 | Blo 4608
#define SMEM_P1 (2 * BUF1)

__global__ void __launch_bounds__(128)
hmma_xv_cd_kernel(const float* __restrict__ x, const float* __restrict__ v,
                  const float* __restrict__ uin, float* __restrict__ uout) {
    extern __shared__ char smc[];
    __shared__ float bs[R_][R_];
    __shared__ float inv[R_];

    int tid = threadIdx.x, wid = tid >> 5, lane = tid & 31;
    int g = lane >> 2, t4 = lane & 3, wrow = wid * 16;
    int b = blockIdx.y, m0 = blockIdx.x * 64;

    load_gram(&bs[0][0], b, tid);
    __syncthreads();
    if (tid < R_) inv[tid] = 1.0f / (bs[tid][tid] + L2C + EPSC);
    // inv visibility to the epilogue is ordered by the loop's later syncs.

    const float* xb = x + (size_t)b * M_ * N_;
    const float* vb = v + (size_t)b * N_ * R_;

    int arow = tid >> 4;        // 0..7, rows +8*i
    int aq   = tid & 15;        // float4 col group (16 = 64 cols)

    float acc[4][4] = {};

    float4 px[8], pv[4];
#pragma unroll
    for (int i = 0; i < 8; i++)
        px[i] = *(const float4*)(xb + (size_t)(m0 + arow + 8 * i) * N_ + aq * 4);
#pragma unroll
    for (int i = 0; i < 4; i++) {
        int idx = tid + 128 * i;
        pv[i] = *(const float4*)(vb + (size_t)(idx >> 3) * R_ + (idx & 7) * 4);
    }

    for (int t = 0; t < N_ / KT1; t++) {
        char* buf = smc + (t & 1) * BUF1;
        uint16_t* Ahi = (uint16_t*)(buf);
        uint16_t* Alo = (uint16_t*)(buf + 9216);
        uint16_t* Bhi = (uint16_t*)(buf + 18432);
        uint16_t* Blo = (uint16_t*)(buf + 23040);

        // stage A: fp32 -> bf16 hi/lo
#pragma unroll
        for (int i = 0; i < 8; i++) {
            int row = arow + 8 * i, k = aq * 4;
            uint32_t h01 = pack2bf(px[i].x, px[i].y);
            uint32_t h23 = pack2bf(px[i].z, px[i].w);
            float hx = __uint_as_float(h01 << 16), hy = __uint_as_float(h01 & 0xFFFF0000u);
            float hz = __uint_as_float(h23 << 16), hw = __uint_as_float(h23 & 0xFFFF0000u);
            uint32_t l01 = pack2bf(px[i].x - hx, px[i].y - hy);
            uint32_t l23 = pack2bf(px[i].z - hz, px[i].w - hw);
            *(uint2*)&Ahi[row * AST1 + k] = make_uint2(h01, h23);
            *(uint2*)&Alo[row * AST1 + k] = make_uint2(l01, l23);
        }
        // stage B transposed: v[k][r] -> B[r][k]
#pragma unroll
        for (int i = 0; i < 4; i++) {
            int idx = tid + 128 * i;
            int k = idx >> 3, rq = idx & 7;
            float vals[4] = {pv[i].x, pv[i].y, pv[i].z, pv[i].w};
#pragma unroll
            for (int e = 0; e < 4; e++) {
                int r = rq * 4 + e;
                uint16_t h = cvt1(vals[e]);
                Bhi[r * AST1 + k] = h;
                Blo[r * AST1 + k] = cvt1(vals[e] - bf2f(h));
            }
        }
        __syncthreads();

        if (t + 1 < N_ / KT1) {
            int kb = (t + 1) * KT1;
#pragma unroll
            for (int i = 0; i < 8; i++)
                px[i] = *(const float4*)(xb + (size_t)(m0 + arow + 8 * i) * N_ + kb + aq * 4);
#pragma unroll
            for (int i = 0; i < 4; i++) {
                int idx = tid + 128 * i;
                pv[i] = *(const float4*)(vb + (size_t)(kb + (idx >> 3)) * R_ + (idx & 7) * 4);
            }
        }

#pragma unroll
        for (int kk = 0; kk < KT1 / 16; kk++)
            mma_kstep<AST1>(Ahi, Alo, Bhi, Blo, wrow, g, t4, kk * 16, acc);
        // no trailing sync: ping-pong; buffer reuse at t+2 guarded by sync in t+1.
    }

    __syncthreads();
    fused_cd_epilogue(acc, (float*)smc, bs, inv,
                      uin + ((size_t)b * M_ + m0) * R_,
                      uout + ((size_t)b * M_ + m0) * R_,
                      tid, wrow, g, t4);
}

// ======================= pass 2: vout = CD(x^T @ u, vin) =======================
// grid (N_/64, B_) = 256 CTAs, 128 threads. KT=32, stride 40; fp32 transpose stage.
#define KT2 32
#define AST2 40
#define BUF2 24064   // Ahi 5120 | Alo 5120 | Bhi 2560 | Blo 2560 | stage 8704
#define SMEM_P2 (2 * BUF2)

__global__ void __launch_bounds__(128)
hmma_xtu_cd_kernel(const float* __restrict__ x, const float* __restrict__ u,
                   const float* __restrict__ vin, float* __restrict__ vout) {
    extern __shared__ char smc[];
    __shared__ float bs[R_][R_];
    __shared__ float inv[R_];

    int tid = threadIdx.x, wid = tid >> 5, lane = tid & 31;
    int g = lane >> 2, t4 = lane & 3, wrow = wid * 16;
    int b = blockIdx.y, n0 = blockIdx.x * 64;

    load_gram(&bs[0][0], b, tid);
    __syncthreads();
    if (tid < R_) inv[tid] = 1.0f / (bs[tid][tid] + L2C + EPSC);

    const float* xb = x + (size_t)b * M_ * N_;
    const float* ub = u + (size_t)b * M_ * R_;

    int srow = tid >> 4;        // 0..7, rows +8*i (i<4) -> 32 k rows
    int sq   = tid & 15;        // float4 col (64 n cols)
    int an   = tid >> 1;        // 0..63 transposed-convert n row
    int ah_  = tid & 1;         // k half (16 each)

    float acc[4][4] = {};

    float4 px[4], pu[2];
#pragma unroll
    for (int i = 0; i < 4; i++)
        px[i] = *(const float4*)(xb + (size_t)(srow + 8 * i) * N_ + n0 + sq * 4);
#pragma unroll
    for (int i = 0; i < 2; i++) {
        int idx = tid + 128 * i;
        pu[i] = *(const float4*)(ub + (size_t)(idx >> 3) * R_ + (idx & 7) * 4);
    }

    for (int t = 0; t < N_ / KT2; t++) {
        char* buf = smc + (t & 1) * BUF2;
        uint16_t* Ahi = (uint16_t*)(buf);
        uint16_t* Alo = (uint16_t*)(buf + 5120);
        uint16_t* Bhi = (uint16_t*)(buf + 10240);
        uint16_t* Blo = (uint16_t*)(buf + 12800);
        float (*stage)[68] = (float (*)[68])(buf + 15360);

        // stage fp32 x chunk [32 k][64 n] + B conversion
#pragma unroll
        for (int i = 0; i < 4; i++)
            *(float4*)&stage[srow + 8 * i][sq * 4] = px[i];
#pragma unroll
        for (int i = 0; i < 2; i++) {
            int idx = tid + 128 * i;
            int k = idx >> 3, rq = idx & 7;
            float vals[4] = {pu[i].x, pu[i].y, pu[i].z, pu[i].w};
#pragma unroll
            for (int e = 0; e < 4; e++) {
                int r = rq * 4 + e;
                uint16_t h = cvt1(vals[e]);
                Bhi[r * AST2 + k] = h;
                Blo[r * AST2 + k] = cvt1(vals[e] - bf2f(h));
            }
        }
        __syncthreads();

        if (t + 1 < N_ / KT2) {
            int mb = (t + 1) * KT2;
#pragma unroll
            for (int i = 0; i < 4; i++)
                px[i] = *(const float4*)(xb + (size_t)(mb + srow + 8 * i) * N_ + n0 + sq * 4);
#pragma unroll
            for (int i = 0; i < 2; i++) {
                int idx = tid + 128 * i;
                pu[i] = *(const float4*)(ub + (size_t)(mb + (idx >> 3)) * R_ + (idx & 7) * 4);
            }
        }

        // transposed convert: A[n][k] bf16 hi/lo
#pragma unroll
        for (int j = 0; j < 4; j++) {
            int k0 = ah_ * 16 + j * 4;
            float a0 = stage[k0 + 0][an];
            float a1 = stage[k0 + 1][an];
            float a2 = stage[k0 + 2][an];
            float a3 = stage[k0 + 3][an];
            uint32_t h01 = pack2bf(a0, a1);
            uint32_t h23 = pack2bf(a2, a3);
            float hx = __uint_as_float(h01 << 16), hy = __uint_as_float(h01 & 0xFFFF0000u);
            float hz = __uint_as_float(h23 << 16), hw = __uint_as_float(h23 & 0xFFFF0000u);
            uint32_t l01 = pack2bf(a0 - hx, a1 - hy);
            uint32_t l23 = pack2bf(a2 - hz, a3 - hw);
            *(uint2*)&Ahi[an * AST2 + k0] = make_uint2(h01, h23);
            *(uint2*)&Alo[an * AST2 + k0] = make_uint2(l01, l23);
        }
        __syncthreads();

#pragma unroll
        for (int kk = 0; kk < KT2 / 16; kk++)
            mma_kstep<AST2>(Ahi, Alo, Bhi, Blo, wrow, g, t4, kk * 16, acc);
    }

    __syncthreads();
    fused_cd_epilogue(acc, (float*)smc, bs, inv,
                      vin + ((size_t)b * M_ + n0) * R_,
                      vout + ((size_t)b * M_ + n0) * R_,
                      tid, wrow, g, t4);
}

// ---------------------------------------------------------------------------
extern "C" void kernel_launch(void* const* d_in, const int* in_sizes, int n_in,
                              void* d_out, int out_size) {
    const float* x = (const float*)d_in[0];
    const float* u = (const float*)d_in[1];
    const float* v = (const float*)d_in[2];
    float* uout = (float*)d_out;
    float* vout = uout + (size_t)B_ * M_ * R_;

    cudaFuncSetAttribute(hmma_xv_cd_kernel, cudaFuncAttributeMaxDynamicSharedMemorySize, SMEM_P1);
    cudaFuncSetAttribute(hmma_xtu_cd_kernel, cudaFuncAttributeMaxDynamicSharedMemorySize, SMEM_P2);

    dim3 gg(16, B_);
    dim3 gt(M_ / 64, B_);       // 32 x 8 = 256 CTAs

    // Phase 1: u update (gram of v; fused GEMM+reduce+CD)
    gram_partial_kernel<<<gg, 256>>>(v);
    hmma_xv_cd_kernel<<<gt, 128, SMEM_P1>>>(x, v, u, uout);

    // Phase 2: v update (gram of new u; fused GEMM+reduce+CD)
    gram_partial_kernel<<<gg, 256>>>(uout);
    hmma_xtu_cd_kernel<<<gt, 128, SMEM_P2>>>(x, uout, v, vout);
}

// round 15
// speedup vs baseline: 1.2983x; 1.2983x over previous
#include <cuda_runtime.h>
#include <cstdint>

#define B_ 8
#define M_ 2048
#define N_ 2048
#define R_ 32

#define L1C 10.24f
#define L2C 10.24f
#define EPSC 1e-16f

#define KT 64
#define NCH (N_ / KT)            // 32 chunks
#define AST 72                   // A tile stride (halfwords): 64 + 8 pad
#define BST 40                   // B tile stride: 32 + 8 pad
#define A_BYTES (64 * AST * 2)   // 9216
#define B_BYTES (64 * BST * 2)   // 5120
#define OFF_ALO A_BYTES
#define OFF_BHI (2 * A_BYTES)
#define OFF_BLO (2 * A_BYTES + B_BYTES)
#define BUF (2 * A_BYTES + 2 * B_BYTES)   // 28672
#define SMEM_DYN (2 * BUF)                // 57344

// Scratch (device globals; no allocation allowed)
__device__ float g_bp[16 * B_ * R_ * R_];  // gram partials

// ---- helpers -------------------------------------------------------------
__device__ __forceinline__ uint32_t pack2bf(float lo, float hi) {   // mem order [lo,hi]
    uint32_t r; asm("cvt.rn.bf16x2.f32 %0, %1, %2;" : "=r"(r) : "f"(hi), "f"(lo)); return r;
}
__device__ __forceinline__ void cvt_hilo(float4 xv, uint2& hi, uint2& lo) {
    uint32_t h01 = pack2bf(xv.x, xv.y);
    uint32_t h23 = pack2bf(xv.z, xv.w);
    float hx = __uint_as_float(h01 << 16), hy = __uint_as_float(h01 & 0xFFFF0000u);
    float hz = __uint_as_float(h23 << 16), hw = __uint_as_float(h23 & 0xFFFF0000u);
    uint32_t l01 = pack2bf(xv.x - hx, xv.y - hy);
    uint32_t l23 = pack2bf(xv.z - hz, xv.w - hw);
    hi = make_uint2(h01, h23); lo = make_uint2(l01, l23);
}
__device__ __forceinline__ uint32_t s2u(const void* p) {
    uint32_t a;
    asm("{ .reg .u64 t; cvta.to.shared.u64 t, %1; cvt.u32.u64 %0, t; }" : "=r"(a) : "l"(p));
    return a;
}
__device__ __forceinline__ void ldsm4(uint32_t* r, uint32_t addr) {
    asm volatile("ldmatrix.sync.aligned.m8n8.x4.shared.b16 {%0,%1,%2,%3}, [%4];"
                 : "=r"(r[0]), "=r"(r[1]), "=r"(r[2]), "=r"(r[3]) : "r"(addr));
}
__device__ __forceinline__ void ldsm4t(uint32_t* r, uint32_t addr) {
    asm volatile("ldmatrix.sync.aligned.m8n8.x4.trans.shared.b16 {%0,%1,%2,%3}, [%4];"
                 : "=r"(r[0]), "=r"(r[1]), "=r"(r[2]), "=r"(r[3]) : "r"(addr));
}
__device__ __forceinline__ void mma16816(float* c, const uint32_t* a, uint32_t b0, uint32_t b1) {
    asm volatile(
        "mma.sync.aligned.m16n8k16.row.col.f32.bf16.bf16.f32 "
        "{%0,%1,%2,%3}, {%4,%5,%6,%7}, {%8,%9}, {%0,%1,%2,%3};"
        : "+f"(c[0]), "+f"(c[1]), "+f"(c[2]), "+f"(c[3])
        : "r"(a[0]), "r"(a[1]), "r"(a[2]), "r"(a[3]), "r"(b0), "r"(b1));
}

// ======================= gram partial kernel =======================
#define GCHUNK 128
__global__ void gram_partial_kernel(const float* __restrict__ vin) {
    __shared__ float vs[GCHUNK][R_];
    int b = blockIdx.y, p = blockIdx.x, tid = threadIdx.x;
    const float4* src = (const float4*)(vin + ((size_t)b * N_ + p * GCHUNK) * R_);
    float4* dst = (float4*)&vs[0][0];
#pragma unroll
    for (int i = 0; i < 4; i++) dst[tid + 256 * i] = src[tid + 256 * i];
    __syncthreads();
    int r = tid >> 3, s4 = (tid & 7) * 4;
    float ax = 0.f, ay = 0.f, az = 0.f, aw = 0.f;
#pragma unroll 8
    for (int m = 0; m < GCHUNK; m++) {
        float vr = vs[m][r];
        float4 sv = *(const float4*)&vs[m][s4];
        ax += vr * sv.x; ay += vr * sv.y; az += vr * sv.z; aw += vr * sv.w;
    }
    float* o = g_bp + ((size_t)p * B_ + b) * (R_ * R_) + r * R_ + s4;
    o[0] = ax; o[1] = ay; o[2] = az; o[3] = aw;
}

// ======================= fused GEMM + CD kernel =======================
// TRANSA=false: rows = m, A = x[m][k] natural (k contiguous), normal ldmatrix.
// TRANSA=true:  rows = n, A = x[k=m][n] natural (n contiguous), ldmatrix.trans.
// B = v/u stored natural [k][r] (r contiguous), fragments via ldmatrix.trans.
// 256 threads = 8 warps: wrow=(wid&3)*16, k-half kh=wid>>2 (k-split reduction).
// grid (M_/64, B_) = 256 CTAs, 2 CTAs/SM.
template <bool TRANSA>
__global__ void __launch_bounds__(256, 2)
fused_gemm_cd_kernel(const float* __restrict__ x, const float* __restrict__ w,
                     const float* __restrict__ uin, float* __restrict__ uout) {
    extern __shared__ char smc[];
    __shared__ float bs[R_][R_];
    __shared__ float inv[R_];

    int tid = threadIdx.x, wid = tid >> 5, lane = tid & 31;
    int g = lane >> 2, t4 = lane & 3;
    int wrow = (wid & 3) * 16;
    int kh = wid >> 2;
    int b = blockIdx.y, m0 = blockIdx.x * 64;

    // in-kernel gram reduce (fixed order -> deterministic)
    {
        const float4* bp4 = (const float4*)g_bp;
        float4 s = {0.f, 0.f, 0.f, 0.f};
#pragma unroll
        for (int p = 0; p < 16; p++) {
            float4 t = bp4[((size_t)p * B_ + b) * 256 + tid];
            s.x += t.x; s.y += t.y; s.z += t.z; s.w += t.w;
        }
        ((float4*)&bs[0][0])[tid] = s;
    }
    __syncthreads();
    if (tid < R_) inv[tid] = 1.0f / (bs[tid][tid] + L2C + EPSC);
    // inv visibility to the epilogue ordered by the loop's syncs.

    const float* xb = x + (size_t)b * M_ * N_;
    const float* wb = w + (size_t)b * N_ * R_;

    int arow = tid >> 2;     // 0..63 (A staging row)
    int ac   = tid & 3;      // f4 col base, +4*i

    // lane fragment offsets (halfword units)
    int aoff_l, boff_l;
    if (TRANSA)
        aoff_l = ((lane >> 4) * 8 + (lane & 7)) * AST + wrow + (((lane >> 3) & 1) * 8);
    else
        aoff_l = (wrow + (((lane >> 3) & 1) * 8) + (lane & 7)) * AST + (lane >> 4) * 8;
    boff_l = ((((lane >> 3) & 1) * 8) + (lane & 7)) * BST + (lane >> 4) * 8;

    float acc[4][4] = {};

    float4 px[4], pb[2];
#pragma unroll
    for (int i = 0; i < 4; i++) {
        int c4 = ac + 4 * i;
        px[i] = TRANSA
            ? *(const float4*)(xb + (size_t)arow * N_ + m0 + c4 * 4)
            : *(const float4*)(xb + (size_t)(m0 + arow) * N_ + c4 * 4);
    }
#pragma unroll
    for (int i = 0; i < 2; i++) {
        int idx = tid + 256 * i;
        pb[i] = *(const float4*)(wb + (size_t)(idx >> 3) * R_ + (idx & 7) * 4);
    }

    for (int t = 0; t < NCH; t++) {
        char* buf = smc + (t & 1) * BUF;
        uint16_t* Ahi = (uint16_t*)buf;
        uint16_t* Alo = (uint16_t*)(buf + OFF_ALO);
        uint16_t* Bhi = (uint16_t*)(buf + OFF_BHI);
        uint16_t* Blo = (uint16_t*)(buf + OFF_BLO);

        // stage A (natural layout, bf16 hi/lo)
#pragma unroll
        for (int i = 0; i < 4; i++) {
            int c4 = ac + 4 * i;
            uint2 hi, lo;
            cvt_hilo(px[i], hi, lo);
            *(uint2*)&Ahi[arow * AST + c4 * 4] = hi;
            *(uint2*)&Alo[arow * AST + c4 * 4] = lo;
        }
        // stage B (natural [k][r] layout)
#pragma unroll
        for (int i = 0; i < 2; i++) {
            int idx = tid + 256 * i;
            int k = idx >> 3, r = (idx & 7) * 4;
            uint2 hi, lo;
            cvt_hilo(pb[i], hi, lo);
            *(uint2*)&Bhi[k * BST + r] = hi;
            *(uint2*)&Blo[k * BST + r] = lo;
        }
        __syncthreads();

        // prefetch next chunk (overlaps MMA below)
        if (t + 1 < NCH) {
            int kb = (t + 1) * KT;
#pragma unroll
            for (int i = 0; i < 4; i++) {
                int c4 = ac + 4 * i;
                px[i] = TRANSA
                    ? *(const float4*)(xb + (size_t)(kb + arow) * N_ + m0 + c4 * 4)
                    : *(const float4*)(xb + (size_t)(m0 + arow) * N_ + kb + c4 * 4);
            }
#pragma unroll
            for (int i = 0; i < 2; i++) {
                int idx = tid + 256 * i;
                pb[i] = *(const float4*)(wb + (size_t)(kb + (idx >> 3)) * R_ + (idx & 7) * 4);
            }
        }

        uint32_t aAhi = s2u(Ahi), aAlo = s2u(Alo), aBhi = s2u(Bhi), aBlo = s2u(Blo);
#pragma unroll
        for (int kk = 0; kk < 2; kk++) {
            int k16 = kh * 32 + kk * 16;
            int aoff = TRANSA ? (aoff_l + k16 * AST) : (aoff_l + k16);
            int boff = boff_l + k16 * BST;
            uint32_t ah[4], al[4], bh[8], bl[8];
            if (TRANSA) { ldsm4t(ah, aAhi + 2 * aoff); ldsm4t(al, aAlo + 2 * aoff); }
            else        { ldsm4 (ah, aAhi + 2 * aoff); ldsm4 (al, aAlo + 2 * aoff); }
            ldsm4t(bh,     aBhi + 2 * boff);
            ldsm4t(bh + 4, aBhi + 2 * (boff + 16));
            ldsm4t(bl,     aBlo + 2 * boff);
            ldsm4t(bl + 4, aBlo + 2 * (boff + 16));
#pragma unroll
            for (int j = 0; j < 4; j++) {
                mma16816(acc[j], ah, bh[2 * j], bh[2 * j + 1]);   // hi*hi
                mma16816(acc[j], ah, bl[2 * j], bl[2 * j + 1]);   // hi*lo
                mma16816(acc[j], al, bh[2 * j], bh[2 * j + 1]);   // lo*hi
            }
        }
        // no trailing sync: ping-pong; buffer reuse at t+2 guarded by sync in t+1.
    }

    // ======== fused epilogue: k-half reduction + per-row Gauss-Seidel CD ========
    __syncthreads();                 // all buf reads done before res overwrites buf0
    float* res = (float*)smc;        // [64][33]
    if (kh == 0) {
#pragma unroll
        for (int j = 0; j < 4; j++) {
            int c = j * 8 + t4 * 2;
            res[(wrow + g) * 33 + c]         = acc[j][0];
            res[(wrow + g) * 33 + c + 1]     = acc[j][1];
            res[(wrow + g + 8) * 33 + c]     = acc[j][2];
            res[(wrow + g + 8) * 33 + c + 1] = acc[j][3];
        }
    }
    __syncthreads();
    if (kh == 1) {
#pragma unroll
        for (int j = 0; j < 4; j++) {
            int c = j * 8 + t4 * 2;
            res[(wrow + g) * 33 + c]         += acc[j][0];
            res[(wrow + g) * 33 + c + 1]     += acc[j][1];
            res[(wrow + g + 8) * 33 + c]     += acc[j][2];
            res[(wrow + g + 8) * 33 + c + 1] += acc[j][3];
        }
    }
    __syncthreads();

    if (tid < 64) {
        const float* ur = uin + ((size_t)b * M_ + m0 + tid) * R_;
        const float* arow_p = res + tid * 33;
        float ureg[R_];
#pragma unroll
        for (int i = 0; i < 8; i++) {
            float4 t2 = *(const float4*)(ur + i * 4);
            ureg[4 * i + 0] = t2.x; ureg[4 * i + 1] = t2.y;
            ureg[4 * i + 2] = t2.z; ureg[4 * i + 3] = t2.w;
        }
#pragma unroll
        for (int r = 0; r < R_; r++) {
            float brr = bs[r][r];
            float d0 = 0.f, d1 = 0.f, d2 = 0.f, d3 = 0.f;
#pragma unroll
            for (int k = 0; k < R_; k += 4) {
                d0 += ureg[k + 0] * bs[k + 0][r];
                d1 += ureg[k + 1] * bs[k + 1][r];
                d2 += ureg[k + 2] * bs[k + 2][r];
                d3 += ureg[k + 3] * bs[k + 3][r];
            }
            float dot = (d0 + d1) + (d2 + d3);
            float z = arow_p[r] - (dot - ureg[r] * brr);
            float num = (z > L1C) ? (z - L1C) : ((z < -L1C) ? (z + L1C) : 0.0f);
            ureg[r] = (num + EPSC) * inv[r];
        }
        float* outr = uout + ((size_t)b * M_ + m0 + tid) * R_;
#pragma unroll
        for (int i = 0; i < 8; i++) {
            float4 o = {ureg[4 * i + 0], ureg[4 * i + 1], ureg[4 * i + 2], ureg[4 * i + 3]};
            *(float4*)(outr + i * 4) = o;
        }
    }
}

// ---------------------------------------------------------------------------
extern "C" void kernel_launch(void* const* d_in, const int* in_sizes, int n_in,
                              void* d_out, int out_size) {
    const float* x = (const float*)d_in[0];
    const float* u = (const float*)d_in[1];
    const float* v = (const float*)d_in[2];
    float* uout = (float*)d_out;
    float* vout = uout + (size_t)B_ * M_ * R_;

    cudaFuncSetAttribute(fused_gemm_cd_kernel<false>,
                         cudaFuncAttributeMaxDynamicSharedMemorySize, SMEM_DYN);
    cudaFuncSetAttribute(fused_gemm_cd_kernel<true>,
                         cudaFuncAttributeMaxDynamicSharedMemorySize, SMEM_DYN);

    dim3 gg(16, B_);
    dim3 gt(M_ / 64, B_);    // 32 x 8 = 256 CTAs

    // Phase 1: u update (gram of v; fused GEMM + reduce + CD)
    gram_partial_kernel<<<gg, 256>>>(v);
    fused_gemm_cd_kernel<false><<<gt, 256, SMEM_DYN>>>(x, v, u, uout);

    // Phase 2: v update (gram of new u; fused x^T GEMM via ldmatrix.trans + CD)
    gram_partial_kernel<<<gg, 256>>>(uout);
    fused_gemm_cd_kernel<true><<<gt, 256, SMEM_DYN>>>(x, uout, v, vout);
}

// round 16
// speedup vs baseline: 1.3387x; 1.0311x over previous
#include <cuda_runtime.h>
#include <cstdint>

#define B_ 8
#define M_ 2048
#define N_ 2048
#define R_ 32

#define L1C 10.24f
#define L2C 10.24f
#define EPSC 1e-16f

#define KT 64
#define NCH (N_ / KT)            // 32 chunks
#define AST 72                   // A tile stride (halfwords): 64 + 8 pad
#define BST 40                   // B tile stride: 32 + 8 pad
#define A_BYTES (64 * AST * 2)   // 9216
#define B_BYTES (64 * BST * 2)   // 5120
#define OFF_ALO A_BYTES
#define OFF_BHI (2 * A_BYTES)
#define OFF_BLO (2 * A_BYTES + B_BYTES)
#define BUF (2 * A_BYTES + 2 * B_BYTES)   // 28672
#define SMEM_DYN (2 * BUF)                // 57344 (res[4][64][33]=33792 fits)

// Scratch (device globals; no allocation allowed)
__device__ float g_bp[16 * B_ * R_ * R_];  // gram partials

// ---- helpers -------------------------------------------------------------
__device__ __forceinline__ uint32_t pack2bf(float lo, float hi) {   // mem order [lo,hi]
    uint32_t r; asm("cvt.rn.bf16x2.f32 %0, %1, %2;" : "=r"(r) : "f"(hi), "f"(lo)); return r;
}
__device__ __forceinline__ void cvt_hilo(float4 xv, uint2& hi, uint2& lo) {
    uint32_t h01 = pack2bf(xv.x, xv.y);
    uint32_t h23 = pack2bf(xv.z, xv.w);
    float hx = __uint_as_float(h01 << 16), hy = __uint_as_float(h01 & 0xFFFF0000u);
    float hz = __uint_as_float(h23 << 16), hw = __uint_as_float(h23 & 0xFFFF0000u);
    uint32_t l01 = pack2bf(xv.x - hx, xv.y - hy);
    uint32_t l23 = pack2bf(xv.z - hz, xv.w - hw);
    hi = make_uint2(h01, h23); lo = make_uint2(l01, l23);
}
__device__ __forceinline__ uint32_t s2u(const void* p) {
    uint32_t a;
    asm("{ .reg .u64 t; cvta.to.shared.u64 t, %1; cvt.u32.u64 %0, t; }" : "=r"(a) : "l"(p));
    return a;
}
__device__ __forceinline__ void ldsm4(uint32_t* r, uint32_t addr) {
    asm volatile("ldmatrix.sync.aligned.m8n8.x4.shared.b16 {%0,%1,%2,%3}, [%4];"
                 : "=r"(r[0]), "=r"(r[1]), "=r"(r[2]), "=r"(r[3]) : "r"(addr));
}
__device__ __forceinline__ void ldsm4t(uint32_t* r, uint32_t addr) {
    asm volatile("ldmatrix.sync.aligned.m8n8.x4.trans.shared.b16 {%0,%1,%2,%3}, [%4];"
                 : "=r"(r[0]), "=r"(r[1]), "=r"(r[2]), "=r"(r[3]) : "r"(addr));
}
__device__ __forceinline__ void mma16816(float* c, const uint32_t* a, uint32_t b0, uint32_t b1) {
    asm volatile(
        "mma.sync.aligned.m16n8k16.row.col.f32.bf16.bf16.f32 "
        "{%0,%1,%2,%3}, {%4,%5,%6,%7}, {%8,%9}, {%0,%1,%2,%3};"
        : "+f"(c[0]), "+f"(c[1]), "+f"(c[2]), "+f"(c[3])
        : "r"(a[0]), "r"(a[1]), "r"(a[2]), "r"(a[3]), "r"(b0), "r"(b1));
}

// ======================= gram partial kernel =======================
#define GCHUNK 128
__global__ void gram_partial_kernel(const float* __restrict__ vin) {
    __shared__ float vs[GCHUNK][R_];
    int b = blockIdx.y, p = blockIdx.x, tid = threadIdx.x;
    const float4* src = (const float4*)(vin + ((size_t)b * N_ + p * GCHUNK) * R_);
    float4* dst = (float4*)&vs[0][0];
#pragma unroll
    for (int i = 0; i < 4; i++) dst[tid + 256 * i] = src[tid + 256 * i];
    __syncthreads();
    int r = tid >> 3, s4 = (tid & 7) * 4;
    float ax = 0.f, ay = 0.f, az = 0.f, aw = 0.f;
#pragma unroll 8
    for (int m = 0; m < GCHUNK; m++) {
        float vr = vs[m][r];
        float4 sv = *(const float4*)&vs[m][s4];
        ax += vr * sv.x; ay += vr * sv.y; az += vr * sv.z; aw += vr * sv.w;
    }
    float* o = g_bp + ((size_t)p * B_ + b) * (R_ * R_) + r * R_ + s4;
    o[0] = ax; o[1] = ay; o[2] = az; o[3] = aw;
}

// ======================= fused GEMM + CD kernel =======================
// TRANSA=false: rows = m, A = x[m][k] natural, normal ldmatrix.
// TRANSA=true:  rows = n, A = x[k][n] natural, ldmatrix.trans.
// B = v/u natural [k][r], fragments via ldmatrix.trans.
// 8 warps = 2 row-groups (32 rows each) x 4 k-quarters (16 k each).
// Per warp per chunk: 8 ldsm.x4 -> 24 MMA (B fragments amortized over 32 rows).
// grid (M_/64, B_) = 256 CTAs, 2 CTAs/SM.
template <bool TRANSA>
__global__ void __launch_bounds__(256, 2)
fused_gemm_cd_kernel(const float* __restrict__ x, const float* __restrict__ w,
                     const float* __restrict__ uin, float* __restrict__ uout) {
    extern __shared__ char smc[];
    __shared__ float bs[R_][R_];
    __shared__ float inv[R_];

    int tid = threadIdx.x, wid = tid >> 5, lane = tid & 31;
    int g = lane >> 2, t4 = lane & 3;
    int wrow = (wid & 1) * 32;      // row-group base
    int kq   = wid >> 1;            // k-quarter 0..3
    int b = blockIdx.y, m0 = blockIdx.x * 64;

    // in-kernel gram reduce (fixed order -> deterministic)
    {
        const float4* bp4 = (const float4*)g_bp;
        float4 s = {0.f, 0.f, 0.f, 0.f};
#pragma unroll
        for (int p = 0; p < 16; p++) {
            float4 t = bp4[((size_t)p * B_ + b) * 256 + tid];
            s.x += t.x; s.y += t.y; s.z += t.z; s.w += t.w;
        }
        ((float4*)&bs[0][0])[tid] = s;
    }
    __syncthreads();
    if (tid < R_) inv[tid] = 1.0f / (bs[tid][tid] + L2C + EPSC);
    // inv visibility to the epilogue ordered by the loop's syncs.

    const float* xb = x + (size_t)b * M_ * N_;
    const float* wb = w + (size_t)b * N_ * R_;

    int arow = tid >> 2;     // 0..63 (A staging row)
    int ac   = tid & 3;      // f4 col base, +4*i

    // lane fragment offsets (halfword units); k16 = kq*16 folded in
    int k16 = kq * 16;
    int aoff0, aoff1, boff;
    if (TRANSA) {
        int kr = k16 + (lane >> 4) * 8 + (lane & 7);        // source row = k
        int nb = wrow + (((lane >> 3) & 1) * 8);            // n base
        aoff0 = kr * AST + nb;
        aoff1 = kr * AST + nb + 16;
    } else {
        int rb = wrow + (((lane >> 3) & 1) * 8) + (lane & 7);
        aoff0 = rb * AST + (lane >> 4) * 8 + k16;
        aoff1 = (rb + 16) * AST + (lane >> 4) * 8 + k16;
    }
    boff = (k16 + (((lane >> 3) & 1) * 8) + (lane & 7)) * BST + (lane >> 4) * 8;

    float acc[2][4][4] = {};

    float4 px[4];
#pragma unroll
    for (int i = 0; i < 4; i++) {
        int c4 = ac + 4 * i;
        px[i] = TRANSA
            ? *(const float4*)(xb + (size_t)arow * N_ + m0 + c4 * 4)
            : *(const float4*)(xb + (size_t)(m0 + arow) * N_ + c4 * 4);
    }

    for (int t = 0; t < NCH; t++) {
        char* buf = smc + (t & 1) * BUF;
        uint16_t* Ahi = (uint16_t*)buf;
        uint16_t* Alo = (uint16_t*)(buf + OFF_ALO);
        uint16_t* Bhi = (uint16_t*)(buf + OFF_BHI);
        uint16_t* Blo = (uint16_t*)(buf + OFF_BLO);

        // stage A (natural layout, bf16 hi/lo) from prefetch regs
#pragma unroll
        for (int i = 0; i < 4; i++) {
            int c4 = ac + 4 * i;
            uint2 hi, lo;
            cvt_hilo(px[i], hi, lo);
            *(uint2*)&Ahi[arow * AST + c4 * 4] = hi;
            *(uint2*)&Alo[arow * AST + c4 * 4] = lo;
        }
        // stage B (natural [k][r]); w is L2-resident, load at stage time
#pragma unroll
        for (int i = 0; i < 2; i++) {
            int idx = tid + 256 * i;
            int k = idx >> 3, r = (idx & 7) * 4;
            float4 pbv = *(const float4*)(wb + (size_t)(t * KT + k) * R_ + r);
            uint2 hi, lo;
            cvt_hilo(pbv, hi, lo);
            *(uint2*)&Bhi[k * BST + r] = hi;
            *(uint2*)&Blo[k * BST + r] = lo;
        }
        __syncthreads();

        // prefetch next x chunk (overlaps MMA below)
        if (t + 1 < NCH) {
            int kb = (t + 1) * KT;
#pragma unroll
            for (int i = 0; i < 4; i++) {
                int c4 = ac + 4 * i;
                px[i] = TRANSA
                    ? *(const float4*)(xb + (size_t)(kb + arow) * N_ + m0 + c4 * 4)
                    : *(const float4*)(xb + (size_t)(m0 + arow) * N_ + kb + c4 * 4);
            }
        }

        uint32_t aAhi = s2u(Ahi), aAlo = s2u(Alo), aBhi = s2u(Bhi), aBlo = s2u(Blo);
        uint32_t bh[8], bl[8];
        ldsm4t(bh,     aBhi + 2 * boff);
        ldsm4t(bh + 4, aBhi + 2 * (boff + 16));
        ldsm4t(bl,     aBlo + 2 * boff);
        ldsm4t(bl + 4, aBlo + 2 * (boff + 16));
#pragma unroll
        for (int rt = 0; rt < 2; rt++) {
            int ao = (rt == 0) ? aoff0 : aoff1;
            uint32_t ah[4], al[4];
            if (TRANSA) { ldsm4t(ah, aAhi + 2 * ao); ldsm4t(al, aAlo + 2 * ao); }
            else        { ldsm4 (ah, aAhi + 2 * ao); ldsm4 (al, aAlo + 2 * ao); }
#pragma unroll
            for (int j = 0; j < 4; j++) {
                mma16816(acc[rt][j], ah, bh[2 * j], bh[2 * j + 1]);   // hi*hi
                mma16816(acc[rt][j], ah, bl[2 * j], bl[2 * j + 1]);   // hi*lo
                mma16816(acc[rt][j], al, bh[2 * j], bh[2 * j + 1]);   // lo*hi
            }
        }
        // no trailing sync: ping-pong; buffer reuse at t+2 guarded by sync in t+1.
    }

    // ======== fused epilogue: 4-plane k-split reduction + per-row CD ========
    __syncthreads();                 // all ldsm reads done before res overwrites bufs
    float* res = (float*)smc;        // [4 planes][64][33]
    {
        float* rp = res + kq * (64 * 33);
#pragma unroll
        for (int rt = 0; rt < 2; rt++) {
#pragma unroll
            for (int j = 0; j < 4; j++) {
                int row0 = wrow + rt * 16 + g;
                int c = j * 8 + t4 * 2;
                rp[row0 * 33 + c]           = acc[rt][j][0];
                rp[row0 * 33 + c + 1]       = acc[rt][j][1];
                rp[(row0 + 8) * 33 + c]     = acc[rt][j][2];
                rp[(row0 + 8) * 33 + c + 1] = acc[rt][j][3];
            }
        }
    }
    __syncthreads();

    if (tid < 64) {
        const float* ur = uin + ((size_t)b * M_ + m0 + tid) * R_;
        const float* r0 = res + tid * 33;
        float areg[R_], ureg[R_];
#pragma unroll
        for (int r = 0; r < R_; r++)
            areg[r] = (r0[r] + r0[64 * 33 + r]) + (r0[2 * 64 * 33 + r] + r0[3 * 64 * 33 + r]);
#pragma unroll
        for (int i = 0; i < 8; i++) {
            float4 t2 = *(const float4*)(ur + i * 4);
            ureg[4 * i + 0] = t2.x; ureg[4 * i + 1] = t2.y;
            ureg[4 * i + 2] = t2.z; ureg[4 * i + 3] = t2.w;
        }
#pragma unroll
        for (int r = 0; r < R_; r++) {
            float brr = bs[r][r];
            float d0 = 0.f, d1 = 0.f, d2 = 0.f, d3 = 0.f;
#pragma unroll
            for (int k = 0; k < R_; k += 4) {
                d0 += ureg[k + 0] * bs[k + 0][r];
                d1 += ureg[k + 1] * bs[k + 1][r];
                d2 += ureg[k + 2] * bs[k + 2][r];
                d3 += ureg[k + 3] * bs[k + 3][r];
            }
            float dot = (d0 + d1) + (d2 + d3);
            float z = areg[r] - (dot - ureg[r] * brr);
            float num = (z > L1C) ? (z - L1C) : ((z < -L1C) ? (z + L1C) : 0.0f);
            ureg[r] = (num + EPSC) * inv[r];
        }
        float* outr = uout + ((size_t)b * M_ + m0 + tid) * R_;
#pragma unroll
        for (int i = 0; i < 8; i++) {
            float4 o = {ureg[4 * i + 0], ureg[4 * i + 1], ureg[4 * i + 2], ureg[4 * i + 3]};
            *(float4*)(outr + i * 4) = o;
        }
    }
}

// ---------------------------------------------------------------------------
extern "C" void kernel_launch(void* const* d_in, const int* in_sizes, int n_in,
                              void* d_out, int out_size) {
    const float* x = (const float*)d_in[0];
    const float* u = (const float*)d_in[1];
    const float* v = (const float*)d_in[2];
    float* uout = (float*)d_out;
    float* vout = uout + (size_t)B_ * M_ * R_;

    cudaFuncSetAttribute(fused_gemm_cd_kernel<false>,
                         cudaFuncAttributeMaxDynamicSharedMemorySize, SMEM_DYN);
    cudaFuncSetAttribute(fused_gemm_cd_kernel<true>,
                         cudaFuncAttributeMaxDynamicSharedMemorySize, SMEM_DYN);

    dim3 gg(16, B_);
    dim3 gt(M_ / 64, B_);    // 32 x 8 = 256 CTAs

    // Phase 1: u update (gram of v; fused GEMM + reduce + CD)
    gram_partial_kernel<<<gg, 256>>>(v);
    fused_gemm_cd_kernel<false><<<gt, 256, SMEM_DYN>>>(x, v, u, uout);

    // Phase 2: v update (gram of new u; fused x^T GEMM via ldmatrix.trans + CD)
    gram_partial_kernel<<<gg, 256>>>(uout);
    fused_gemm_cd_kernel<true><<<gt, 256, SMEM_DYN>>>(x, uout, v, vout);
}